// round 16
// baseline (speedup 1.0000x reference)
#include <cuda_runtime.h>
#include <cuda_bf16.h>
#include <math.h>
#include <stdint.h>

#define Bb 64
#define LL 196
#define TT 32
#define MAXT 31
#define ED 2048
#define AD 512
#define DD 512
#define VV 10000
#define XK 3072
#define GSPLIT 12
#define FCLD 10112

// d_out layout (float32): predictions, caps, dl, alphas, sort_idx
#define PRED_OFF  0
#define CAPS_OFF  (Bb*MAXT*VV)
#define DL_OFF    (CAPS_OFF + Bb*TT)
#define ALPHA_OFF (DL_OFF + Bb)
#define SIDX_OFF  (ALPHA_OFF + Bb*MAXT*LL)

// ------------------- static device scratch -------------------
__device__ int   g_sidx[Bb];
__device__ int   g_nb[MAXT];
__device__ float g_mean[Bb*ED];
__device__ float g_h[Bb*DD];
__device__ float g_c[Bb*DD];
__device__ float g_WaEnc[(size_t)Bb*LL*AD];
__device__ float g_Wcat[(size_t)2048*XK];
__device__ float g_beta[Bb];
__device__ float g_energy[Bb*LL];
__device__ float g_xcat[Bb*XK];                    // [emb | context | h]
__device__ float g_gatesPart[GSPLIT*Bb*2048];
__device__ float g_fcPart[2*Bb*FCLD];
__device__ float g_initPart[2*16*Bb*DD];

// packed bf16-split (setup only): uint2 {hi_pair, lo_pair}
__device__ uint2 g_encPk[(size_t)Bb*LL*(ED/2)];
__device__ uint2 g_WaT  [(size_t)AD*(ED/2)];

__device__ __forceinline__ float sigmoidf_(float x){ return 1.0f/(1.0f+expf(-x)); }
__device__ __forceinline__ float tanh_hw(float x){
    float r; asm("tanh.approx.f32 %0, %1;" : "=f"(r) : "f"(x)); return r;
}
__device__ __forceinline__ uint2 packsplit(float x0, float x1){
    __nv_bfloat16 h0 = __float2bfloat16_rn(x0);
    __nv_bfloat16 h1 = __float2bfloat16_rn(x1);
    __nv_bfloat16 l0 = __float2bfloat16_rn(x0 - __bfloat162float(h0));
    __nv_bfloat16 l1 = __float2bfloat16_rn(x1 - __bfloat162float(h1));
    uint2 u;
    u.x = (uint32_t)__bfloat16_as_ushort(h0) | ((uint32_t)__bfloat16_as_ushort(h1) << 16);
    u.y = (uint32_t)__bfloat16_as_ushort(l0) | ((uint32_t)__bfloat16_as_ushort(l1) << 16);
    return u;
}
__device__ __forceinline__ void mma16816(float* c,
    uint32_t a0, uint32_t a1, uint32_t a2, uint32_t a3, uint32_t b0, uint32_t b1)
{
    asm volatile(
        "mma.sync.aligned.m16n8k16.row.col.f32.bf16.bf16.f32 "
        "{%0,%1,%2,%3},{%4,%5,%6,%7},{%8,%9},{%0,%1,%2,%3};"
        : "+f"(c[0]), "+f"(c[1]), "+f"(c[2]), "+f"(c[3])
        : "r"(a0), "r"(a1), "r"(a2), "r"(a3), "r"(b0), "r"(b1));
}

// ------------------- sort -------------------
__global__ void k_sort(const int* __restrict__ lengths, const int* __restrict__ captions,
                       float* __restrict__ out)
{
    __shared__ int slen[Bb];
    __shared__ int sdl[Bb];
    int i = threadIdx.x;
    slen[i] = lengths[i];
    __syncthreads();
    int li = slen[i];
    int rank = 0;
    #pragma unroll 8
    for (int j = 0; j < Bb; j++) {
        int lj = slen[j];
        if (lj > li || (lj == li && j < i)) rank++;
    }
    g_sidx[rank] = i;
    __syncthreads();
    int src = g_sidx[i];
    int dl  = slen[src] - 1;
    sdl[i] = dl;
    out[DL_OFF + i]   = (float)dl;
    out[SIDX_OFF + i] = (float)src;
    for (int t2 = 0; t2 < TT; t2++)
        out[CAPS_OFF + i*TT + t2] = (float)captions[src*TT + t2];
    __syncthreads();
    if (i < MAXT) {
        int c = 0;
        for (int j = 0; j < Bb; j++) if (sdl[j] > i) c++;
        g_nb[i] = c;
    }
}

// ------------------- setup: Wcat, enc pack, WaT pack, mean -------------------
__global__ void k_wcat(const float* __restrict__ W_ih, const float* __restrict__ W_hh)
{
    int j = blockIdx.x;
    for (int k = threadIdx.x; k < XK; k += 256)
        g_Wcat[(size_t)j*XK + k] = (k < 2560) ? W_ih[(size_t)j*2560 + k]
                                              : W_hh[(size_t)j*512 + (k - 2560)];
}

__global__ void k_cvt_enc(const float* __restrict__ enc)
{
    int row = blockIdx.x;
    const float* r = enc + (size_t)row*ED;
    uint2* o = g_encPk + (size_t)row*(ED/2);
    #pragma unroll
    for (int i = 0; i < 4; i++) {
        int p = threadIdx.x + i*256;
        o[p] = packsplit(r[2*p], r[2*p+1]);
    }
}

__global__ void k_cvt_waT(const float* __restrict__ W)
{
    int kp = blockIdx.x;
    int n  = blockIdx.y*256 + threadIdx.x;
    float v0 = W[(size_t)(2*kp)*AD + n];
    float v1 = W[(size_t)(2*kp+1)*AD + n];
    g_WaT[(size_t)n*(ED/2) + kp] = packsplit(v0, v1);
}

__global__ void k_mean(const float* __restrict__ enc)
{
    int b = blockIdx.x;
    int e = blockIdx.y*256 + threadIdx.x;
    const float* p = enc + (size_t)g_sidx[b]*LL*ED + e;
    float s = 0.f;
    #pragma unroll 4
    for (int l = 0; l < LL; l++) s += p[(size_t)l*ED];
    g_mean[b*ED + e] = s * (1.0f/196.0f);
}

// ------------------- setup mma GEMM for WaEnc -------------------
__global__ void __launch_bounds__(256) wgemm_waenc(
    const uint2* __restrict__ A, const uint2* __restrict__ BT, float* __restrict__ C)
{
    const int ldap = ED/2, ldbp = ED/2, ldc = AD;
    int tid = threadIdx.x;
    int wid = tid >> 5, lane = tid & 31;
    int g = lane >> 2, t = lane & 3;
    int m0 = blockIdx.y*64 + (wid & 3)*16;
    int n0 = blockIdx.x*128 + (wid >> 2)*64;

    int rA = m0 + g, rB = m0 + g + 8;
    rA = g_sidx[rA / LL]*LL + (rA % LL);
    rB = g_sidx[rB / LL]*LL + (rB % LL);
    const uint2* Arow0 = A + (size_t)rA*ldap + t;
    const uint2* Arow1 = A + (size_t)rB*ldap + t;

    float c[8][4];
    #pragma unroll
    for (int j = 0; j < 8; j++){ c[j][0]=0.f;c[j][1]=0.f;c[j][2]=0.f;c[j][3]=0.f; }

    for (int kp = 0; kp < ED/2; kp += 8) {
        uint2 A0 = Arow0[kp], A2 = Arow0[kp+4];
        uint2 A1 = Arow1[kp], A3 = Arow1[kp+4];
        #pragma unroll
        for (int j = 0; j < 8; j++) {
            const uint2* Br = BT + (size_t)(n0 + j*8 + g)*ldbp + t;
            uint2 B0 = Br[kp], B1 = Br[kp+4];
            mma16816(c[j], A0.x, A1.x, A2.x, A3.x, B0.x, B1.x);
            mma16816(c[j], A0.x, A1.x, A2.x, A3.x, B0.y, B1.y);
            mma16816(c[j], A0.y, A1.y, A2.y, A3.y, B0.x, B1.x);
        }
    }
    #pragma unroll
    for (int j = 0; j < 8; j++) {
        int n = n0 + j*8 + 2*t;
        float* cr0 = C + (size_t)(m0 + g)*ldc + n;
        float* cr1 = C + (size_t)(m0 + g + 8)*ldc + n;
        cr0[0] = c[j][0]; cr0[1] = c[j][1];
        cr1[0] = c[j][2]; cr1[1] = c[j][3];
    }
}

// ------------------- FP32 GEMM (R5 version, reg prefetch) -------------------
template<bool TRANSB>
__global__ void __launch_bounds__(256) gemm2(
    const float* __restrict__ A, const float* __restrict__ Bm,
    float* __restrict__ C, int M, int N, int K, int lda, int ldc)
{
    const int BM=64, BN=128, BK=16;
    __shared__ __align__(16) float As[BK][BM];
    __shared__ __align__(16) float Bs[BK][BN];
    int bn = blockIdx.x*BN, bm = blockIdx.y*BM;
    int kPer = K / gridDim.z;
    int k0 = blockIdx.z * kPer;
    int nIter = kPer / BK;
    C += (size_t)blockIdx.z * (size_t)M * (size_t)ldc;

    int tid = threadIdx.x;
    int tx = tid & 15, ty = tid >> 4;
    int a_m = tid >> 2, a_k = (tid & 3) << 2;
    int b_k = tid >> 4;
    int b_n = (tid & 15) << 2;
    int r2  = tid >> 2;

    size_t arow = (size_t)(bm + a_m)*(size_t)lda;

    float4 aR, bR0, bR1;
    {
        int kk0 = k0;
        aR = *(const float4*)(A + arow + kk0 + a_k);
        if (TRANSB) {
            bR0 = *(const float4*)(Bm + (size_t)(bn + r2)      * (size_t)K + kk0 + a_k);
            bR1 = *(const float4*)(Bm + (size_t)(bn + 64 + r2) * (size_t)K + kk0 + a_k);
        } else {
            const float* br = Bm + (size_t)(kk0 + b_k)*(size_t)N;
            bR0 = *(const float4*)(br + bn + b_n);
            bR1 = *(const float4*)(br + bn + 64 + b_n);
        }
    }

    float acc[4][8];
    #pragma unroll
    for (int i = 0; i < 4; i++)
        #pragma unroll
        for (int j = 0; j < 8; j++) acc[i][j] = 0.f;

    for (int it = 0; it < nIter; it++) {
        As[a_k+0][a_m] = aR.x; As[a_k+1][a_m] = aR.y;
        As[a_k+2][a_m] = aR.z; As[a_k+3][a_m] = aR.w;
        if (TRANSB) {
            Bs[a_k+0][r2] = bR0.x; Bs[a_k+1][r2] = bR0.y;
            Bs[a_k+2][r2] = bR0.z; Bs[a_k+3][r2] = bR0.w;
            Bs[a_k+0][64+r2] = bR1.x; Bs[a_k+1][64+r2] = bR1.y;
            Bs[a_k+2][64+r2] = bR1.z; Bs[a_k+3][64+r2] = bR1.w;
        } else {
            *(float4*)&Bs[b_k][b_n]      = bR0;
            *(float4*)&Bs[b_k][64 + b_n] = bR1;
        }
        __syncthreads();

        if (it + 1 < nIter) {
            int kk0 = k0 + (it+1)*BK;
            aR = *(const float4*)(A + arow + kk0 + a_k);
            if (TRANSB) {
                bR0 = *(const float4*)(Bm + (size_t)(bn + r2)      * (size_t)K + kk0 + a_k);
                bR1 = *(const float4*)(Bm + (size_t)(bn + 64 + r2) * (size_t)K + kk0 + a_k);
            } else {
                const float* br = Bm + (size_t)(kk0 + b_k)*(size_t)N;
                bR0 = *(const float4*)(br + bn + b_n);
                bR1 = *(const float4*)(br + bn + 64 + b_n);
            }
        }

        #pragma unroll
        for (int kk = 0; kk < BK; kk++) {
            float4 av = *(const float4*)&As[kk][ty*4];
            float4 b0 = *(const float4*)&Bs[kk][tx*4];
            float4 b1 = *(const float4*)&Bs[kk][64 + tx*4];
            float a[4] = {av.x, av.y, av.z, av.w};
            #pragma unroll
            for (int i = 0; i < 4; i++) {
                acc[i][0] += a[i]*b0.x; acc[i][1] += a[i]*b0.y;
                acc[i][2] += a[i]*b0.z; acc[i][3] += a[i]*b0.w;
                acc[i][4] += a[i]*b1.x; acc[i][5] += a[i]*b1.y;
                acc[i][6] += a[i]*b1.z; acc[i][7] += a[i]*b1.w;
            }
        }
        __syncthreads();
    }

    int n0 = bn + tx*4, n1 = bn + 64 + tx*4;
    #pragma unroll
    for (int i = 0; i < 4; i++) {
        int m = bm + ty*4 + i;
        float* cr = C + (size_t)m*(size_t)ldc;
        *(float4*)(cr + n0) = *(float4*)&acc[i][0];
        *(float4*)(cr + n1) = *(float4*)&acc[i][4];
    }
}

// ------------------- fc partial gemm device body -------------------
__device__ void fc_partial(const float* __restrict__ A, const float* __restrict__ Bm,
                           int nt, int z)
{
    const int BK = 16;
    __shared__ __align__(16) float As[BK][64];
    __shared__ __align__(16) float Bs[BK][128];
    int bn = nt*128;
    int k0 = z*256;
    float* C = g_fcPart + (size_t)z*Bb*FCLD;

    int tid = threadIdx.x;
    int tx = tid & 15, ty = tid >> 4;
    int a_m = tid >> 2, a_k = (tid & 3) << 2;
    int b_k = tid >> 4;
    int b_n = (tid & 15) << 2;
    size_t arow = (size_t)a_m * DD;

    float acc[4][8];
    #pragma unroll
    for (int i = 0; i < 4; i++)
        #pragma unroll
        for (int j = 0; j < 8; j++) acc[i][j] = 0.f;

    for (int it = 0; it < 16; it++) {
        int kk0 = k0 + it*BK;
        float4 av = *(const float4*)(A + arow + kk0 + a_k);
        const float* br = Bm + (size_t)(kk0 + b_k)*VV;
        int n0 = bn + b_n, n1 = bn + 64 + b_n;
        float4 bv0, bv1;
        if (n0 + 3 < VV) bv0 = *(const float4*)(br + n0);
        else { bv0.x = n0<VV?br[n0]:0.f; bv0.y = n0+1<VV?br[n0+1]:0.f;
               bv0.z = n0+2<VV?br[n0+2]:0.f; bv0.w = 0.f; }
        if (n1 + 3 < VV) bv1 = *(const float4*)(br + n1);
        else { bv1.x = n1<VV?br[n1]:0.f; bv1.y = n1+1<VV?br[n1+1]:0.f;
               bv1.z = n1+2<VV?br[n1+2]:0.f; bv1.w = 0.f; }
        As[a_k+0][a_m] = av.x; As[a_k+1][a_m] = av.y;
        As[a_k+2][a_m] = av.z; As[a_k+3][a_m] = av.w;
        *(float4*)&Bs[b_k][b_n]      = bv0;
        *(float4*)&Bs[b_k][64 + b_n] = bv1;
        __syncthreads();
        #pragma unroll
        for (int kk = 0; kk < BK; kk++) {
            float4 a4 = *(const float4*)&As[kk][ty*4];
            float4 b0 = *(const float4*)&Bs[kk][tx*4];
            float4 b1 = *(const float4*)&Bs[kk][64 + tx*4];
            float a[4] = {a4.x, a4.y, a4.z, a4.w};
            #pragma unroll
            for (int i = 0; i < 4; i++) {
                acc[i][0] += a[i]*b0.x; acc[i][1] += a[i]*b0.y;
                acc[i][2] += a[i]*b0.z; acc[i][3] += a[i]*b0.w;
                acc[i][4] += a[i]*b1.x; acc[i][5] += a[i]*b1.y;
                acc[i][6] += a[i]*b1.z; acc[i][7] += a[i]*b1.w;
            }
        }
        __syncthreads();
    }

    int n0 = bn + tx*4, n1 = bn + 64 + tx*4;
    #pragma unroll
    for (int i = 0; i < 4; i++) {
        int m = ty*4 + i;
        float* cr = C + (size_t)m*FCLD;
        *(float4*)(cr + n0) = *(float4*)&acc[i][0];
        *(float4*)(cr + n1) = *(float4*)&acc[i][4];
    }
}

// ======= k_attn: in-block hU + prestep + energy  [64 blocks] =======
__global__ void __launch_bounds__(256) k_attn(
    const int* __restrict__ caps, const float* __restrict__ embT,
    const float* __restrict__ fb_W, const float* __restrict__ fb_b,
    const float* __restrict__ w_att, const float* __restrict__ U_a, int t)
{
    int b = blockIdx.x;
    if (b >= g_nb[t]) return;
    int tid = threadIdx.x;

    __shared__ __align__(16) float sh[DD];
    __shared__ __align__(16) float sHU[AD];
    __shared__ __align__(16) float sW[AD];
    __shared__ float sB[8];
    int warp = tid >> 5, lane = tid & 31;

    sh[tid]       = g_h[b*DD + tid];
    sh[256 + tid] = g_h[b*DD + 256 + tid];
    sW[tid]       = w_att[tid];
    sW[256 + tid] = w_att[256 + tid];
    // emb copy (independent of h)
    int cap = caps[g_sidx[b]*TT + t];
    if (tid < 128)
        ((float4*)(g_xcat + (size_t)b*XK))[tid] =
            ((const float4*)(embT + (size_t)cap*DD))[tid];
    __syncthreads();

    // h copy + beta
    if (tid >= 128)
        ((float4*)(g_xcat + (size_t)b*XK + 2560))[tid - 128] =
            ((const float4*)sh)[tid - 128];
    {
        float s = sh[tid]*fb_W[tid] + sh[256 + tid]*fb_W[256 + tid];
        #pragma unroll
        for (int o = 16; o > 0; o >>= 1) s += __shfl_xor_sync(0xffffffffu, s, o);
        if (lane == 0) sB[warp] = s;
    }
    // hU in-block: thread computes a = tid and a = 256+tid (coalesced U_a rows)
    {
        float acc0 = 0.f, acc1 = 0.f;
        #pragma unroll 8
        for (int k = 0; k < DD; k++) {
            float hv = sh[k];
            const float* ur = U_a + (size_t)k*AD;
            acc0 += hv * ur[tid];
            acc1 += hv * ur[256 + tid];
        }
        sHU[tid] = acc0;
        sHU[256 + tid] = acc1;
    }
    __syncthreads();
    if (tid == 0) {
        float tot = 0.f;
        #pragma unroll
        for (int w = 0; w < 8; w++) tot += sB[w];
        g_beta[b] = sigmoidf_(tot + fb_b[0]);
    }

    // energies
    for (int l = warp; l < LL; l += 8) {
        const float* wa = g_WaEnc + ((size_t)b*LL + l)*AD;
        float acc = 0.f;
        #pragma unroll
        for (int i = 0; i < 16; i++) {
            int a = lane + 32*i;
            acc += tanh_hw(wa[a] + sHU[a]) * sW[a];
        }
        #pragma unroll
        for (int o = 16; o > 0; o >>= 1) acc += __shfl_xor_sync(0xffffffffu, acc, o);
        if (lane == 0) g_energy[b*LL + l] = acc;
    }
}

// ------------------- context body (R13) -------------------
__device__ void context_body(const float* __restrict__ enc, float* __restrict__ out,
                             int b, int ec, int t)
{
    int tid = threadIdx.x;
    __shared__ __align__(16) float sAl[LL];
    __shared__ float sred[8];

    float v = (tid < LL) ? g_energy[b*LL + tid] : -3.4e38f;
    float m = v;
    #pragma unroll
    for (int o = 16; o > 0; o >>= 1) m = fmaxf(m, __shfl_xor_sync(0xffffffffu, m, o));
    if ((tid & 31) == 0) sred[tid >> 5] = m;
    __syncthreads();
    if (tid < 8) {
        float mm = sred[tid];
        #pragma unroll
        for (int o = 4; o > 0; o >>= 1) mm = fmaxf(mm, __shfl_xor_sync(0xffu, mm, o));
        if (tid == 0) sred[0] = mm;
    }
    __syncthreads();
    float mx = sred[0];
    __syncthreads();

    float p = (tid < LL) ? expf(v - mx) : 0.f;
    float s = p;
    #pragma unroll
    for (int o = 16; o > 0; o >>= 1) s += __shfl_xor_sync(0xffffffffu, s, o);
    if ((tid & 31) == 0) sred[tid >> 5] = s;
    __syncthreads();
    if (tid < 8) {
        float ss = sred[tid];
        #pragma unroll
        for (int o = 4; o > 0; o >>= 1) ss += __shfl_xor_sync(0xffu, ss, o);
        if (tid == 0) sred[0] = ss;
    }
    __syncthreads();
    float alpha = p / sred[0];
    if (tid < LL) sAl[tid] = alpha;
    if (ec == 0 && tid < LL)
        out[ALPHA_OFF + ((size_t)b*MAXT + t)*LL + tid] = alpha;
    __syncthreads();

    int e = ec*256 + tid;
    const float* pe = enc + (size_t)g_sidx[b]*LL*ED + e;
    float acc = 0.f;
    #pragma unroll 4
    for (int l = 0; l < LL; l++) acc += sAl[l] * pe[(size_t)l*ED];
    g_xcat[(size_t)b*XK + 512 + e] = acc * g_beta[b];
}

// ======= fused: context(t) [512 blocks] + fc partial(t-1) [158 blocks] =======
__global__ void __launch_bounds__(256) k_ctxfc(
    const float* __restrict__ enc, const float* __restrict__ fc_W,
    float* __restrict__ out, int t)
{
    int bid = blockIdx.x;
    if (bid < 512) {
        int b = bid >> 3, ec = bid & 7;
        if (b >= g_nb[t]) return;
        context_body(enc, out, b, ec, t);
    } else {
        if (t == 0) return;
        int f = bid - 512;           // 0..157
        fc_partial(g_h, fc_W, f % 79, f / 79);
    }
}

// standalone fc partial wrapper (for final t)
__global__ void __launch_bounds__(256) k_fcpart(const float* __restrict__ fc_W)
{
    fc_partial(g_h, fc_W, blockIdx.x % 79, blockIdx.x / 79);
}

// ------------------- h0/c0 reduce + tanh -------------------
__global__ void k_init(const float* __restrict__ ih_b, const float* __restrict__ ic_b)
{
    int b = blockIdx.x;
    for (int j = threadIdx.x; j < DD; j += 256) {
        float sh = 0.f, sc = 0.f;
        #pragma unroll
        for (int ks = 0; ks < 16; ks++) {
            sh += g_initPart[((size_t)ks*Bb + b)*DD + j];
            sc += g_initPart[((size_t)(16+ks)*Bb + b)*DD + j];
        }
        g_h[b*DD + j] = tanhf(sh + ih_b[j]);
        g_c[b*DD + j] = tanhf(sc + ic_b[j]);
    }
}

// ------------------- fcred device body -------------------
__device__ void fcred_body(const float* __restrict__ fc_b, float* __restrict__ out,
                           int b, int nchunk, int t)
{
    if (b >= g_nb[t]) return;
    int n = nchunk*256 + threadIdx.x;
    if (n >= VV) return;
    float v = g_fcPart[(size_t)b*FCLD + n]
            + g_fcPart[(size_t)(Bb + b)*FCLD + n]
            + fc_b[n];
    out[PRED_OFF + (size_t)b*MAXT*VV + (size_t)t*VV + n] = v;
}

// ======= fused: lstm(t) [64 blocks] + fcred(t-1) [2560 blocks] =======
__global__ void k_lstmfc(const float* __restrict__ b_ih, const float* __restrict__ b_hh,
                         const float* __restrict__ fc_b, float* __restrict__ out, int t)
{
    int bid = blockIdx.x;
    int tid = threadIdx.x;
    if (bid >= 64) {
        if (t == 0) return;
        int f = bid - 64;
        fcred_body(fc_b, out, f / 40, f % 40, t - 1);
        return;
    }
    int b = bid;
    if (b >= g_nb[t]) return;
    #pragma unroll
    for (int jj = 0; jj < 2; jj++) {
        int j = tid + jj*256;
        float gi = b_ih[j]        + b_hh[j];
        float gf = b_ih[512 + j]  + b_hh[512 + j];
        float gg = b_ih[1024 + j] + b_hh[1024 + j];
        float go = b_ih[1536 + j] + b_hh[1536 + j];
        #pragma unroll
        for (int ks = 0; ks < GSPLIT; ks++) {
            const float* gp = g_gatesPart + ((size_t)ks*Bb + b)*2048;
            gi += gp[j]; gf += gp[512 + j]; gg += gp[1024 + j]; go += gp[1536 + j];
        }
        float i_ = sigmoidf_(gi);
        float f_ = sigmoidf_(gf);
        float g2 = tanhf(gg);
        float o_ = sigmoidf_(go);
        float c = f_ * g_c[b*DD + j] + i_ * g2;
        float h = o_ * tanhf(c);
        g_c[b*DD + j] = c;
        g_h[b*DD + j] = h;
    }
}

// standalone fcred (final t)
__global__ void k_fcred(const float* __restrict__ fc_b, float* __restrict__ out, int t)
{
    fcred_body(fc_b, out, blockIdx.x / 40, blockIdx.x % 40, t);
}

// ------------------- host -------------------
extern "C" void kernel_launch(void* const* d_in, const int* in_sizes, int n_in,
                              void* d_out_v, int out_size)
{
    const float* enc   = (const float*)d_in[0];
    const int*   caps  = (const int*)  d_in[1];
    const int*   lens  = (const int*)  d_in[2];
    const float* embT  = (const float*)d_in[3];
    const float* W_a   = (const float*)d_in[4];
    const float* U_a   = (const float*)d_in[5];
    const float* w_att = (const float*)d_in[6];
    const float* fb_W  = (const float*)d_in[7];
    const float* fb_b  = (const float*)d_in[8];
    const float* W_ih  = (const float*)d_in[9];
    const float* W_hh  = (const float*)d_in[10];
    const float* b_ih  = (const float*)d_in[11];
    const float* b_hh  = (const float*)d_in[12];
    const float* fc_W  = (const float*)d_in[13];
    const float* fc_b  = (const float*)d_in[14];
    const float* ih_W  = (const float*)d_in[15];
    const float* ih_b  = (const float*)d_in[16];
    const float* ic_W  = (const float*)d_in[17];
    const float* ic_b  = (const float*)d_in[18];
    float* out = (float*)d_out_v;

    void *pMean, *pH, *pWaEnc, *pWcat, *pXcat, *pGates, *pInit, *pEncPk, *pWaT;
    cudaGetSymbolAddress(&pMean,  g_mean);
    cudaGetSymbolAddress(&pH,     g_h);
    cudaGetSymbolAddress(&pWaEnc, g_WaEnc);
    cudaGetSymbolAddress(&pWcat,  g_Wcat);
    cudaGetSymbolAddress(&pXcat,  g_xcat);
    cudaGetSymbolAddress(&pGates, g_gatesPart);
    cudaGetSymbolAddress(&pInit,  g_initPart);
    cudaGetSymbolAddress(&pEncPk, g_encPk);
    cudaGetSymbolAddress(&pWaT,   g_WaT);

    cudaMemsetAsync(out, 0, (size_t)out_size * sizeof(float), 0);

    k_sort<<<1, 64>>>(lens, caps, out);
    k_wcat<<<2048, 256>>>(W_ih, W_hh);
    k_cvt_enc<<<Bb*LL, 256>>>(enc);
    k_cvt_waT<<<dim3(ED/2, 2), 256>>>(W_a);
    k_mean<<<dim3(64,8), 256>>>(enc);

    gemm2<false><<<dim3(4,1,16), 256>>>(
        (const float*)pMean, ih_W, (float*)pInit, 64, 512, 2048, 2048, 512);
    gemm2<false><<<dim3(4,1,16), 256>>>(
        (const float*)pMean, ic_W, (float*)pInit + (size_t)16*64*512, 64, 512, 2048, 2048, 512);
    k_init<<<64, 256>>>(ih_b, ic_b);

    wgemm_waenc<<<dim3(4, 196), 256>>>(
        (const uint2*)pEncPk, (const uint2*)pWaT, (float*)pWaEnc);

    for (int t = 0; t < MAXT; t++) {
        // attn: in-block hU + prestep + energies (no hU GEMM launch)
        k_attn<<<64, 256>>>(caps, embT, fb_W, fb_b, w_att, U_a, t);

        // context(t) + fc gemm partials(t-1)
        k_ctxfc<<<512 + 158, 256>>>(enc, fc_W, out, t);

        // gates partials: 64x2048, K=3072 (xcat @ Wcat^T), z=12 (fp32)
        gemm2<true><<<dim3(16,1,GSPLIT), 256>>>(
            (const float*)pXcat, (const float*)pWcat, (float*)pGates,
            64, 2048, XK, XK, 2048);

        // lstm(t) + fcred(t-1)
        k_lstmfc<<<64 + 2560, 256>>>(b_ih, b_hh, fc_b, out, t);
    }

    // final fc for t = MAXT-1
    k_fcpart<<<158, 256>>>(fc_W);
    k_fcred<<<2560, 256>>>(fc_b, out, MAXT-1);
}

// round 17
// speedup vs baseline: 1.5263x; 1.5263x over previous
#include <cuda_runtime.h>
#include <cuda_bf16.h>
#include <math.h>
#include <stdint.h>

#define Bb 64
#define LL 196
#define TT 32
#define MAXT 31
#define ED 2048
#define AD 512
#define DD 512
#define VV 10000
#define XK 3072
#define HSPLIT 8
#define GZ 8
#define FCLD 10112

// d_out layout (float32): predictions, caps, dl, alphas, sort_idx
#define PRED_OFF  0
#define CAPS_OFF  (Bb*MAXT*VV)
#define DL_OFF    (CAPS_OFF + Bb*TT)
#define ALPHA_OFF (DL_OFF + Bb)
#define SIDX_OFF  (ALPHA_OFF + Bb*MAXT*LL)

// ------------------- static device scratch -------------------
__device__ int   g_sidx[Bb];
__device__ int   g_nb[MAXT];
__device__ float g_mean[Bb*ED];
__device__ float g_h[Bb*DD];
__device__ float g_c[Bb*DD];
__device__ float g_WaEnc[(size_t)Bb*LL*AD];
__device__ float g_hUpart[HSPLIT*Bb*AD];
__device__ float g_beta[Bb];
__device__ float g_energy[Bb*LL];
__device__ float g_gatesPart[GZ*Bb*2048];
__device__ float g_fcPart[2*Bb*FCLD];
__device__ float g_initPart[2*16*Bb*DD];

// packed bf16-split: uint2 {hi_pair, lo_pair}
__device__ uint2 g_encPk[(size_t)Bb*LL*(ED/2)];
__device__ uint2 g_WaT  [(size_t)AD*(ED/2)];
__device__ uint2 g_WcatPk[(size_t)2048*(XK/2)];
__device__ uint2 g_xcatPk[Bb*(XK/2)];          // [emb 0..255 | ctx 256..1279 | h 1280..1535]

__device__ __forceinline__ float sigmoidf_(float x){ return 1.0f/(1.0f+expf(-x)); }
__device__ __forceinline__ float tanh_hw(float x){
    float r; asm("tanh.approx.f32 %0, %1;" : "=f"(r) : "f"(x)); return r;
}
__device__ __forceinline__ uint2 packsplit(float x0, float x1){
    __nv_bfloat16 h0 = __float2bfloat16_rn(x0);
    __nv_bfloat16 h1 = __float2bfloat16_rn(x1);
    __nv_bfloat16 l0 = __float2bfloat16_rn(x0 - __bfloat162float(h0));
    __nv_bfloat16 l1 = __float2bfloat16_rn(x1 - __bfloat162float(h1));
    uint2 u;
    u.x = (uint32_t)__bfloat16_as_ushort(h0) | ((uint32_t)__bfloat16_as_ushort(h1) << 16);
    u.y = (uint32_t)__bfloat16_as_ushort(l0) | ((uint32_t)__bfloat16_as_ushort(l1) << 16);
    return u;
}
__device__ __forceinline__ void mma16816(float* c,
    uint32_t a0, uint32_t a1, uint32_t a2, uint32_t a3, uint32_t b0, uint32_t b1)
{
    asm volatile(
        "mma.sync.aligned.m16n8k16.row.col.f32.bf16.bf16.f32 "
        "{%0,%1,%2,%3},{%4,%5,%6,%7},{%8,%9},{%0,%1,%2,%3};"
        : "+f"(c[0]), "+f"(c[1]), "+f"(c[2]), "+f"(c[3])
        : "r"(a0), "r"(a1), "r"(a2), "r"(a3), "r"(b0), "r"(b1));
}

// ------------------- sort -------------------
__global__ void k_sort(const int* __restrict__ lengths, const int* __restrict__ captions,
                       float* __restrict__ out)
{
    __shared__ int slen[Bb];
    __shared__ int sdl[Bb];
    int i = threadIdx.x;
    slen[i] = lengths[i];
    __syncthreads();
    int li = slen[i];
    int rank = 0;
    #pragma unroll 8
    for (int j = 0; j < Bb; j++) {
        int lj = slen[j];
        if (lj > li || (lj == li && j < i)) rank++;
    }
    g_sidx[rank] = i;
    __syncthreads();
    int src = g_sidx[i];
    int dl  = slen[src] - 1;
    sdl[i] = dl;
    out[DL_OFF + i]   = (float)dl;
    out[SIDX_OFF + i] = (float)src;
    for (int t2 = 0; t2 < TT; t2++)
        out[CAPS_OFF + i*TT + t2] = (float)captions[src*TT + t2];
    __syncthreads();
    if (i < MAXT) {
        int c = 0;
        for (int j = 0; j < Bb; j++) if (sdl[j] > i) c++;
        g_nb[i] = c;
    }
}

// ------------------- setup conversions -------------------
__global__ void k_cvt_wcat(const float* __restrict__ W_ih, const float* __restrict__ W_hh)
{
    int n = blockIdx.x;
    uint2* o = g_WcatPk + (size_t)n*(XK/2);
    #pragma unroll
    for (int i = 0; i < 6; i++) {
        int kp = threadIdx.x + i*256;
        int k0 = 2*kp;
        float v0 = (k0   < 2560) ? W_ih[(size_t)n*2560 + k0]   : W_hh[(size_t)n*512 + (k0-2560)];
        float v1 = (k0+1 < 2560) ? W_ih[(size_t)n*2560 + k0+1] : W_hh[(size_t)n*512 + (k0+1-2560)];
        o[kp] = packsplit(v0, v1);
    }
}

__global__ void k_cvt_enc(const float* __restrict__ enc)
{
    int row = blockIdx.x;
    const float* r = enc + (size_t)row*ED;
    uint2* o = g_encPk + (size_t)row*(ED/2);
    #pragma unroll
    for (int i = 0; i < 4; i++) {
        int p = threadIdx.x + i*256;
        o[p] = packsplit(r[2*p], r[2*p+1]);
    }
}

__global__ void k_cvt_waT(const float* __restrict__ W)
{
    int kp = blockIdx.x;
    int n  = blockIdx.y*256 + threadIdx.x;
    float v0 = W[(size_t)(2*kp)*AD + n];
    float v1 = W[(size_t)(2*kp+1)*AD + n];
    g_WaT[(size_t)n*(ED/2) + kp] = packsplit(v0, v1);
}

__global__ void k_mean(const float* __restrict__ enc)
{
    int b = blockIdx.x;
    int e = blockIdx.y*256 + threadIdx.x;
    const float* p = enc + (size_t)g_sidx[b]*LL*ED + e;
    float s = 0.f;
    #pragma unroll 4
    for (int l = 0; l < LL; l++) s += p[(size_t)l*ED];
    g_mean[b*ED + e] = s * (1.0f/196.0f);
}

// ------------------- setup mma GEMM for WaEnc -------------------
__global__ void __launch_bounds__(256) wgemm_waenc(
    const uint2* __restrict__ A, const uint2* __restrict__ BT, float* __restrict__ C)
{
    const int ldap = ED/2, ldbp = ED/2, ldc = AD;
    int tid = threadIdx.x;
    int wid = tid >> 5, lane = tid & 31;
    int g = lane >> 2, t = lane & 3;
    int m0 = blockIdx.y*64 + (wid & 3)*16;
    int n0 = blockIdx.x*128 + (wid >> 2)*64;

    int rA = m0 + g, rB = m0 + g + 8;
    rA = g_sidx[rA / LL]*LL + (rA % LL);
    rB = g_sidx[rB / LL]*LL + (rB % LL);
    const uint2* Arow0 = A + (size_t)rA*ldap + t;
    const uint2* Arow1 = A + (size_t)rB*ldap + t;

    float c[8][4];
    #pragma unroll
    for (int j = 0; j < 8; j++){ c[j][0]=0.f;c[j][1]=0.f;c[j][2]=0.f;c[j][3]=0.f; }

    for (int kp = 0; kp < ED/2; kp += 8) {
        uint2 A0 = Arow0[kp], A2 = Arow0[kp+4];
        uint2 A1 = Arow1[kp], A3 = Arow1[kp+4];
        #pragma unroll
        for (int j = 0; j < 8; j++) {
            const uint2* Br = BT + (size_t)(n0 + j*8 + g)*ldbp + t;
            uint2 B0 = Br[kp], B1 = Br[kp+4];
            mma16816(c[j], A0.x, A1.x, A2.x, A3.x, B0.x, B1.x);
            mma16816(c[j], A0.x, A1.x, A2.x, A3.x, B0.y, B1.y);
            mma16816(c[j], A0.y, A1.y, A2.y, A3.y, B0.x, B1.x);
        }
    }
    #pragma unroll
    for (int j = 0; j < 8; j++) {
        int n = n0 + j*8 + 2*t;
        float* cr0 = C + (size_t)(m0 + g)*ldc + n;
        float* cr1 = C + (size_t)(m0 + g + 8)*ldc + n;
        cr0[0] = c[j][0]; cr0[1] = c[j][1];
        cr1[0] = c[j][2]; cr1[1] = c[j][3];
    }
}

// ------------------- FP32 GEMM (init h0/c0 and hU) -------------------
__global__ void __launch_bounds__(256) gemm2(
    const float* __restrict__ A, const float* __restrict__ Bm,
    float* __restrict__ C, int M, int N, int K, int lda, int ldc)
{
    const int BM=64, BN=128, BK=16;
    __shared__ __align__(16) float As[BK][BM];
    __shared__ __align__(16) float Bs[BK][BN];
    int bn = blockIdx.x*BN, bm = blockIdx.y*BM;
    int kPer = K / gridDim.z;
    int k0 = blockIdx.z * kPer;
    int nIter = kPer / BK;
    C += (size_t)blockIdx.z * (size_t)M * (size_t)ldc;

    int tid = threadIdx.x;
    int tx = tid & 15, ty = tid >> 4;
    int a_m = tid >> 2, a_k = (tid & 3) << 2;
    int b_k = tid >> 4;
    int b_n = (tid & 15) << 2;

    size_t arow = (size_t)(bm + a_m)*(size_t)lda;

    float4 aR, bR0, bR1;
    {
        aR = *(const float4*)(A + arow + k0 + a_k);
        const float* br = Bm + (size_t)(k0 + b_k)*(size_t)N;
        bR0 = *(const float4*)(br + bn + b_n);
        bR1 = *(const float4*)(br + bn + 64 + b_n);
    }

    float acc[4][8];
    #pragma unroll
    for (int i = 0; i < 4; i++)
        #pragma unroll
        for (int j = 0; j < 8; j++) acc[i][j] = 0.f;

    for (int it = 0; it < nIter; it++) {
        As[a_k+0][a_m] = aR.x; As[a_k+1][a_m] = aR.y;
        As[a_k+2][a_m] = aR.z; As[a_k+3][a_m] = aR.w;
        *(float4*)&Bs[b_k][b_n]      = bR0;
        *(float4*)&Bs[b_k][64 + b_n] = bR1;
        __syncthreads();

        if (it + 1 < nIter) {
            int kk0 = k0 + (it+1)*BK;
            aR = *(const float4*)(A + arow + kk0 + a_k);
            const float* br = Bm + (size_t)(kk0 + b_k)*(size_t)N;
            bR0 = *(const float4*)(br + bn + b_n);
            bR1 = *(const float4*)(br + bn + 64 + b_n);
        }

        #pragma unroll
        for (int kk = 0; kk < BK; kk++) {
            float4 av = *(const float4*)&As[kk][ty*4];
            float4 b0 = *(const float4*)&Bs[kk][tx*4];
            float4 b1 = *(const float4*)&Bs[kk][64 + tx*4];
            float a[4] = {av.x, av.y, av.z, av.w};
            #pragma unroll
            for (int i = 0; i < 4; i++) {
                acc[i][0] += a[i]*b0.x; acc[i][1] += a[i]*b0.y;
                acc[i][2] += a[i]*b0.z; acc[i][3] += a[i]*b0.w;
                acc[i][4] += a[i]*b1.x; acc[i][5] += a[i]*b1.y;
                acc[i][6] += a[i]*b1.z; acc[i][7] += a[i]*b1.w;
            }
        }
        __syncthreads();
    }

    int n0 = bn + tx*4, n1 = bn + 64 + tx*4;
    #pragma unroll
    for (int i = 0; i < 4; i++) {
        int m = bm + ty*4 + i;
        float* cr = C + (size_t)m*(size_t)ldc;
        *(float4*)(cr + n0) = *(float4*)&acc[i][0];
        *(float4*)(cr + n1) = *(float4*)&acc[i][4];
    }
}

// ------------------- fc partial gemm device body (fp32, R13) -------------------
__device__ void fc_partial(const float* __restrict__ A, const float* __restrict__ Bm,
                           int nt, int z)
{
    const int BK = 16;
    __shared__ __align__(16) float As[BK][64];
    __shared__ __align__(16) float Bs[BK][128];
    int bn = nt*128;
    int k0 = z*256;
    float* C = g_fcPart + (size_t)z*Bb*FCLD;

    int tid = threadIdx.x;
    int tx = tid & 15, ty = tid >> 4;
    int a_m = tid >> 2, a_k = (tid & 3) << 2;
    int b_k = tid >> 4;
    int b_n = (tid & 15) << 2;
    size_t arow = (size_t)a_m * DD;

    float acc[4][8];
    #pragma unroll
    for (int i = 0; i < 4; i++)
        #pragma unroll
        for (int j = 0; j < 8; j++) acc[i][j] = 0.f;

    for (int it = 0; it < 16; it++) {
        int kk0 = k0 + it*BK;
        float4 av = *(const float4*)(A + arow + kk0 + a_k);
        const float* br = Bm + (size_t)(kk0 + b_k)*VV;
        int n0 = bn + b_n, n1 = bn + 64 + b_n;
        float4 bv0, bv1;
        if (n0 + 3 < VV) bv0 = *(const float4*)(br + n0);
        else { bv0.x = n0<VV?br[n0]:0.f; bv0.y = n0+1<VV?br[n0+1]:0.f;
               bv0.z = n0+2<VV?br[n0+2]:0.f; bv0.w = 0.f; }
        if (n1 + 3 < VV) bv1 = *(const float4*)(br + n1);
        else { bv1.x = n1<VV?br[n1]:0.f; bv1.y = n1+1<VV?br[n1+1]:0.f;
               bv1.z = n1+2<VV?br[n1+2]:0.f; bv1.w = 0.f; }
        As[a_k+0][a_m] = av.x; As[a_k+1][a_m] = av.y;
        As[a_k+2][a_m] = av.z; As[a_k+3][a_m] = av.w;
        *(float4*)&Bs[b_k][b_n]      = bv0;
        *(float4*)&Bs[b_k][64 + b_n] = bv1;
        __syncthreads();
        #pragma unroll
        for (int kk = 0; kk < BK; kk++) {
            float4 a4 = *(const float4*)&As[kk][ty*4];
            float4 b0 = *(const float4*)&Bs[kk][tx*4];
            float4 b1 = *(const float4*)&Bs[kk][64 + tx*4];
            float a[4] = {a4.x, a4.y, a4.z, a4.w};
            #pragma unroll
            for (int i = 0; i < 4; i++) {
                acc[i][0] += a[i]*b0.x; acc[i][1] += a[i]*b0.y;
                acc[i][2] += a[i]*b0.z; acc[i][3] += a[i]*b0.w;
                acc[i][4] += a[i]*b1.x; acc[i][5] += a[i]*b1.y;
                acc[i][6] += a[i]*b1.z; acc[i][7] += a[i]*b1.w;
            }
        }
        __syncthreads();
    }

    int n0 = bn + tx*4, n1 = bn + 64 + tx*4;
    #pragma unroll
    for (int i = 0; i < 4; i++) {
        int m = ty*4 + i;
        float* cr = C + (size_t)m*FCLD;
        *(float4*)(cr + n0) = *(float4*)&acc[i][0];
        *(float4*)(cr + n1) = *(float4*)&acc[i][4];
    }
}

// ------------------- energies + prestep (packed emb/h, beta) [64x4 blocks] -------------------
__global__ void k_energy(const int* __restrict__ captions, const float* __restrict__ embT,
                         const float* __restrict__ fb_W, const float* __restrict__ fb_b,
                         const float* __restrict__ w_att, int t)
{
    int b = blockIdx.x;
    if (b >= g_nb[t]) return;
    int yc = blockIdx.y;
    int tid = threadIdx.x;
    __shared__ float sHU[AD];
    __shared__ float sW[AD];
    __shared__ float sB[8];

    for (int a = tid; a < AD; a += 256) {
        float s = 0.f;
        #pragma unroll
        for (int ks = 0; ks < HSPLIT; ks++)
            s += g_hUpart[((size_t)ks*Bb + b)*AD + a];
        sHU[a] = s;
        sW[a]  = w_att[a];
    }

    if (yc == 0) {
        int cap = captions[g_sidx[b]*TT + t];
        float h0 = g_h[b*DD + 2*tid], h1 = g_h[b*DD + 2*tid + 1];
        g_xcatPk[(size_t)b*1536 + tid] =
            packsplit(embT[(size_t)cap*DD + 2*tid], embT[(size_t)cap*DD + 2*tid + 1]);
        g_xcatPk[(size_t)b*1536 + 1280 + tid] = packsplit(h0, h1);
        float s = h0*fb_W[2*tid] + h1*fb_W[2*tid+1];
        #pragma unroll
        for (int o = 16; o > 0; o >>= 1) s += __shfl_xor_sync(0xffffffffu, s, o);
        if ((tid & 31) == 0) sB[tid >> 5] = s;
    }
    __syncthreads();
    if (yc == 0 && tid == 0) {
        float tot = 0.f;
        #pragma unroll
        for (int w = 0; w < 8; w++) tot += sB[w];
        g_beta[b] = sigmoidf_(tot + fb_b[0]);
    }

    int warp = tid >> 5, lane = tid & 31;
    int lend = min(yc*49 + 49, LL);
    for (int li = yc*49 + warp; li < lend; li += 8) {
        const float* wa = g_WaEnc + ((size_t)b*LL + li)*AD;
        float acc = 0.f;
        #pragma unroll 4
        for (int a = lane; a < AD; a += 32)
            acc += tanh_hw(wa[a] + sHU[a]) * sW[a];
        #pragma unroll
        for (int o = 16; o > 0; o >>= 1) acc += __shfl_xor_sync(0xffffffffu, acc, o);
        if (lane == 0) g_energy[b*LL + li] = acc;
    }
}

// ------------------- context body (pair version, packed write) -------------------
__device__ void context_body(const float* __restrict__ enc, float* __restrict__ out,
                             int b, int ec, int t)
{
    int tid = threadIdx.x;
    __shared__ __align__(16) float sAl[LL];
    __shared__ float sred[8];

    float v = (tid < LL) ? g_energy[b*LL + tid] : -3.4e38f;
    float m = v;
    #pragma unroll
    for (int o = 16; o > 0; o >>= 1) m = fmaxf(m, __shfl_xor_sync(0xffffffffu, m, o));
    if ((tid & 31) == 0) sred[tid >> 5] = m;
    __syncthreads();
    if (tid < 8) {
        float mm = sred[tid];
        #pragma unroll
        for (int o = 4; o > 0; o >>= 1) mm = fmaxf(mm, __shfl_xor_sync(0xffu, mm, o));
        if (tid == 0) sred[0] = mm;
    }
    __syncthreads();
    float mx = sred[0];
    __syncthreads();

    float p = (tid < LL) ? expf(v - mx) : 0.f;
    float s = p;
    #pragma unroll
    for (int o = 16; o > 0; o >>= 1) s += __shfl_xor_sync(0xffffffffu, s, o);
    if ((tid & 31) == 0) sred[tid >> 5] = s;
    __syncthreads();
    if (tid < 8) {
        float ss = sred[tid];
        #pragma unroll
        for (int o = 4; o > 0; o >>= 1) ss += __shfl_xor_sync(0xffu, ss, o);
        if (tid == 0) sred[0] = ss;
    }
    __syncthreads();
    float alpha = p / sred[0];
    if (tid < LL) sAl[tid] = alpha;
    if (ec == 0 && tid < LL)
        out[ALPHA_OFF + ((size_t)b*MAXT + t)*LL + tid] = alpha;
    __syncthreads();

    int pp = ec*256 + tid;                         // pair 0..1023
    float beta = g_beta[b];
    const float* pe = enc + (size_t)g_sidx[b]*LL*ED + 2*pp;
    float a0 = 0.f, a1 = 0.f;
    #pragma unroll 4
    for (int l = 0; l < LL; l++) {
        float2 vv = *(const float2*)(pe + (size_t)l*ED);
        float al = sAl[l];
        a0 += al*vv.x; a1 += al*vv.y;
    }
    g_xcatPk[(size_t)b*1536 + 256 + pp] = packsplit(a0*beta, a1*beta);
}

// ======= fused: context(t) [256 blocks, y=4] + fc partial(t-1) [158 blocks] =======
__global__ void __launch_bounds__(256) k_ctxfc(
    const float* __restrict__ enc, const float* __restrict__ fc_W,
    float* __restrict__ out, int t)
{
    int bid = blockIdx.x;
    if (bid < 256) {
        int b = bid >> 2, ec = bid & 3;
        if (b >= g_nb[t]) return;
        context_body(enc, out, b, ec, t);
    } else {
        if (t == 0) return;
        int f = bid - 256;           // 0..157
        fc_partial(g_h, fc_W, f % 79, f / 79);
    }
}

// standalone fc partial wrapper (for final t)
__global__ void __launch_bounds__(256) k_fcpart(const float* __restrict__ fc_W)
{
    fc_partial(g_h, fc_W, blockIdx.x % 79, blockIdx.x / 79);
}

// ======= gates mma: bf16-split, conflict-free smem B, partials z=0..7 [128 blocks] =======
__global__ void __launch_bounds__(256) k_gates()
{
    int nti = blockIdx.x & 15, z = blockIdx.x >> 4;
    __shared__ __align__(16) uint32_t BsH[16][136];
    __shared__ __align__(16) uint32_t BsL[16][136];
    int tid = threadIdx.x;
    int wid = tid >> 5, lane = tid & 31;
    int g = lane >> 2, tq = lane & 3;
    int m0 = (wid & 3)*16;
    int n0loc = (wid >> 2)*64;
    int nbase = nti*128;
    int kp0 = z*192;

    const uint2* Arow0 = g_xcatPk + (size_t)(m0 + g)*1536 + tq;
    const uint2* Arow1 = g_xcatPk + (size_t)(m0 + g + 8)*1536 + tq;
    int br = tid >> 1, bhalf = (tid & 1)*8;

    float c[8][4];
    #pragma unroll
    for (int j = 0; j < 8; j++){ c[j][0]=0.f;c[j][1]=0.f;c[j][2]=0.f;c[j][3]=0.f; }

    for (int ch = 0; ch < 12; ch++) {
        int kp = kp0 + ch*16;
        __syncthreads();
        const uint2* src = g_WcatPk + (size_t)(nbase + br)*1536 + kp + bhalf;
        #pragma unroll
        for (int q = 0; q < 8; q++) {
            uint2 v = src[q];
            BsH[bhalf + q][br] = v.x;
            BsL[bhalf + q][br] = v.y;
        }
        __syncthreads();
        #pragma unroll
        for (int kk = 0; kk < 16; kk += 8) {
            uint2 A0 = Arow0[kp+kk], A2 = Arow0[kp+kk+4];
            uint2 A1 = Arow1[kp+kk], A3 = Arow1[kp+kk+4];
            #pragma unroll
            for (int j = 0; j < 8; j++) {
                int r = n0loc + j*8 + g;
                uint32_t B0h = BsH[kk+tq][r],   B1h = BsH[kk+tq+4][r];
                uint32_t B0l = BsL[kk+tq][r],   B1l = BsL[kk+tq+4][r];
                mma16816(c[j], A0.x, A1.x, A2.x, A3.x, B0h, B1h);
                mma16816(c[j], A0.x, A1.x, A2.x, A3.x, B0l, B1l);
                mma16816(c[j], A0.y, A1.y, A2.y, A3.y, B0h, B1h);
            }
        }
    }
    float* C = g_gatesPart + (size_t)z*Bb*2048;
    #pragma unroll
    for (int j = 0; j < 8; j++) {
        int n = nbase + n0loc + j*8 + 2*tq;
        float* cr0 = C + (size_t)(m0 + g)*2048 + n;
        float* cr1 = C + (size_t)(m0 + g + 8)*2048 + n;
        cr0[0] = c[j][0]; cr0[1] = c[j][1];
        cr1[0] = c[j][2]; cr1[1] = c[j][3];
    }
}

// ------------------- h0/c0 reduce + tanh -------------------
__global__ void k_init(const float* __restrict__ ih_b, const float* __restrict__ ic_b)
{
    int b = blockIdx.x;
    for (int j = threadIdx.x; j < DD; j += 256) {
        float sh = 0.f, sc = 0.f;
        #pragma unroll
        for (int ks = 0; ks < 16; ks++) {
            sh += g_initPart[((size_t)ks*Bb + b)*DD + j];
            sc += g_initPart[((size_t)(16+ks)*Bb + b)*DD + j];
        }
        g_h[b*DD + j] = tanhf(sh + ih_b[j]);
        g_c[b*DD + j] = tanhf(sc + ic_b[j]);
    }
}

// ------------------- fcred device body -------------------
__device__ void fcred_body(const float* __restrict__ fc_b, float* __restrict__ out,
                           int b, int nchunk, int t)
{
    if (b >= g_nb[t]) return;
    int n = nchunk*256 + threadIdx.x;
    if (n >= VV) return;
    float v = g_fcPart[(size_t)b*FCLD + n]
            + g_fcPart[(size_t)(Bb + b)*FCLD + n]
            + fc_b[n];
    out[PRED_OFF + (size_t)b*MAXT*VV + (size_t)t*VV + n] = v;
}

// ======= fused: lstm(t) [64 blocks] + fcred(t-1) [2560 blocks] =======
__global__ void k_lstmfc(const float* __restrict__ b_ih, const float* __restrict__ b_hh,
                         const float* __restrict__ fc_b, float* __restrict__ out, int t)
{
    int bid = blockIdx.x;
    int tid = threadIdx.x;
    if (bid >= 64) {
        if (t == 0) return;
        int f = bid - 64;
        fcred_body(fc_b, out, f / 40, f % 40, t - 1);
        return;
    }
    int b = bid;
    if (b >= g_nb[t]) return;
    #pragma unroll
    for (int jj = 0; jj < 2; jj++) {
        int j = tid + jj*256;
        float gi = b_ih[j]        + b_hh[j];
        float gf = b_ih[512 + j]  + b_hh[512 + j];
        float gg = b_ih[1024 + j] + b_hh[1024 + j];
        float go = b_ih[1536 + j] + b_hh[1536 + j];
        #pragma unroll
        for (int ks = 0; ks < GZ; ks++) {
            const float* gp = g_gatesPart + ((size_t)ks*Bb + b)*2048;
            gi += gp[j]; gf += gp[512 + j]; gg += gp[1024 + j]; go += gp[1536 + j];
        }
        float i_ = sigmoidf_(gi);
        float f_ = sigmoidf_(gf);
        float g2 = tanhf(gg);
        float o_ = sigmoidf_(go);
        float c = f_ * g_c[b*DD + j] + i_ * g2;
        float h = o_ * tanhf(c);
        g_c[b*DD + j] = c;
        g_h[b*DD + j] = h;
    }
}

// standalone fcred (final t)
__global__ void k_fcred(const float* __restrict__ fc_b, float* __restrict__ out, int t)
{
    fcred_body(fc_b, out, blockIdx.x / 40, blockIdx.x % 40, t);
}

// ------------------- host -------------------
extern "C" void kernel_launch(void* const* d_in, const int* in_sizes, int n_in,
                              void* d_out_v, int out_size)
{
    const float* enc   = (const float*)d_in[0];
    const int*   caps  = (const int*)  d_in[1];
    const int*   lens  = (const int*)  d_in[2];
    const float* embT  = (const float*)d_in[3];
    const float* W_a   = (const float*)d_in[4];
    const float* U_a   = (const float*)d_in[5];
    const float* w_att = (const float*)d_in[6];
    const float* fb_W  = (const float*)d_in[7];
    const float* fb_b  = (const float*)d_in[8];
    const float* W_ih  = (const float*)d_in[9];
    const float* W_hh  = (const float*)d_in[10];
    const float* b_ih  = (const float*)d_in[11];
    const float* b_hh  = (const float*)d_in[12];
    const float* fc_W  = (const float*)d_in[13];
    const float* fc_b  = (const float*)d_in[14];
    const float* ih_W  = (const float*)d_in[15];
    const float* ih_b  = (const float*)d_in[16];
    const float* ic_W  = (const float*)d_in[17];
    const float* ic_b  = (const float*)d_in[18];
    float* out = (float*)d_out_v;

    void *pMean, *pH, *pWaEnc, *pHU, *pInit, *pEncPk, *pWaT;
    cudaGetSymbolAddress(&pMean,  g_mean);
    cudaGetSymbolAddress(&pH,     g_h);
    cudaGetSymbolAddress(&pWaEnc, g_WaEnc);
    cudaGetSymbolAddress(&pHU,    g_hUpart);
    cudaGetSymbolAddress(&pInit,  g_initPart);
    cudaGetSymbolAddress(&pEncPk, g_encPk);
    cudaGetSymbolAddress(&pWaT,   g_WaT);

    cudaMemsetAsync(out, 0, (size_t)out_size * sizeof(float), 0);

    k_sort<<<1, 64>>>(lens, caps, out);
    k_cvt_wcat<<<2048, 256>>>(W_ih, W_hh);
    k_cvt_enc<<<Bb*LL, 256>>>(enc);
    k_cvt_waT<<<dim3(ED/2, 2), 256>>>(W_a);
    k_mean<<<dim3(64,8), 256>>>(enc);

    gemm2<<<dim3(4,1,16), 256>>>(
        (const float*)pMean, ih_W, (float*)pInit, 64, 512, 2048, 2048, 512);
    gemm2<<<dim3(4,1,16), 256>>>(
        (const float*)pMean, ic_W, (float*)pInit + (size_t)16*64*512, 64, 512, 2048, 2048, 512);
    k_init<<<64, 256>>>(ih_b, ic_b);

    wgemm_waenc<<<dim3(4, 196), 256>>>(
        (const uint2*)pEncPk, (const uint2*)pWaT, (float*)pWaEnc);

    for (int t = 0; t < MAXT; t++) {
        // hU partials: 64x512, K=512, z=8 (fp32)
        gemm2<<<dim3(4,1,HSPLIT), 256>>>(
            (const float*)pH, U_a, (float*)pHU, 64, 512, 512, 512, 512);

        // energies + packed emb/h prestep + beta
        k_energy<<<dim3(64,4), 256>>>(caps, embT, fb_W, fb_b, w_att, t);

        // context(t) [pairs] + fc gemm partials(t-1)
        k_ctxfc<<<256 + 158, 256>>>(enc, fc_W, out, t);

        // gates partials via tensor cores, z=8
        k_gates<<<16*GZ, 256>>>();

        // lstm(t) + fcred(t-1)
        k_lstmfc<<<64 + 2560, 256>>>(b_ih, b_hh, fc_b, out, t);
    }

    // final fc for t = MAXT-1
    k_fcpart<<<158, 256>>>(fc_W);
    k_fcred<<<2560, 256>>>(fc_b, out, MAXT-1);
}